// round 9
// baseline (speedup 1.0000x reference)
#include <cuda_runtime.h>

#define N_USERS 200000
#define N_SPOTS 50000
#define N_NODES (N_USERS + N_SPOTS)
#define N_EDGES 3200000
#define D 64
#define D4 (D / 4)   // 16 float4 per row

// Fixed-stride adjacency. Degrees ~ Poisson(16)/Poisson(64); caps 96/192 have
// ~e^-50 overflow probability; writes are bounds-guarded (clamped, never OOB).
#define CAP_U 96
#define CAP_S 192

// Scratch (__device__ globals; allocations forbidden).
__device__ int   g_cnt[N_NODES];     // [users | spots]
__device__ float g_isq[N_NODES];
__device__ int   g_adj_u[N_USERS * CAP_U];  // user -> spot partners
__device__ int   g_adj_s[N_SPOTS * CAP_S];  // spot -> user partners
__device__ float g_ux[N_USERS * D];  // pre-scaled user rows
__device__ float g_sx[N_SPOTS * D];  // pre-scaled spot rows

__device__ __forceinline__ void add_f32x2(unsigned long long& a, unsigned long long b) {
    asm("add.rn.f32x2 %0, %0, %1;" : "+l"(a) : "l"(b));
}
__device__ __forceinline__ unsigned long long mul_f32x2(unsigned long long a, unsigned long long b) {
    unsigned long long r;
    asm("mul.rn.f32x2 %0, %1, %2;" : "=l"(r) : "l"(a), "l"(b));
    return r;
}

__global__ void __launch_bounds__(256) zero_kernel() {
    int i = blockIdx.x * blockDim.x + threadIdx.x;
    if (i < N_NODES) g_cnt[i] = 0;
}

// Fused degree+fill: one atomic produces slot AND final degree. 4 edges per
// thread via int4 loads; 8 independent atomics then 8 guarded stores.
__global__ void __launch_bounds__(256) fill_kernel(const int4* __restrict__ user_idx4,
                                                   const int4* __restrict__ spot_idx4) {
    int t = blockIdx.x * blockDim.x + threadIdx.x;
    if (t >= N_EDGES / 4) return;
    int4 u = __ldg(&user_idx4[t]);
    int4 s = __ldg(&spot_idx4[t]);

    int au0 = atomicAdd(&g_cnt[u.x], 1);
    int au1 = atomicAdd(&g_cnt[u.y], 1);
    int au2 = atomicAdd(&g_cnt[u.z], 1);
    int au3 = atomicAdd(&g_cnt[u.w], 1);
    int as0 = atomicAdd(&g_cnt[N_USERS + s.x], 1);
    int as1 = atomicAdd(&g_cnt[N_USERS + s.y], 1);
    int as2 = atomicAdd(&g_cnt[N_USERS + s.z], 1);
    int as3 = atomicAdd(&g_cnt[N_USERS + s.w], 1);

    if (au0 < CAP_U) g_adj_u[u.x * CAP_U + au0] = s.x;
    if (au1 < CAP_U) g_adj_u[u.y * CAP_U + au1] = s.y;
    if (au2 < CAP_U) g_adj_u[u.z * CAP_U + au2] = s.z;
    if (au3 < CAP_U) g_adj_u[u.w * CAP_U + au3] = s.w;
    if (as0 < CAP_S) g_adj_s[s.x * CAP_S + as0] = u.x;
    if (as1 < CAP_S) g_adj_s[s.y * CAP_S + as1] = u.y;
    if (as2 < CAP_S) g_adj_s[s.z * CAP_S + as2] = u.z;
    if (as3 < CAP_S) g_adj_s[s.w * CAP_S + as3] = u.w;
}

// Pre-scale all rows by inv-sqrt degree; materialize g_isq.
__global__ void __launch_bounds__(256) prescale_kernel(const float* __restrict__ user_x,
                                                       const float* __restrict__ spot_x) {
    int i = blockIdx.x * blockDim.x + threadIdx.x;
    if (i >= N_NODES * D4) return;
    int node = i >> 4;
    int dg = g_cnt[node];
    float q = rsqrtf(dg == 0 ? 1e-6f : (float)dg);
    if ((i & 15) == 0) g_isq[node] = q;

    float4 v;
    if (node < N_USERS) {
        v = __ldg(&((const float4*)user_x)[i]);
        v.x *= q; v.y *= q; v.z *= q; v.w *= q;
        ((float4*)g_ux)[i] = v;
    } else {
        int j = i - N_USERS * D4;
        v = __ldg(&((const float4*)spot_x)[j]);
        v.x *= q; v.y *= q; v.z *= q; v.w *= q;
        ((float4*)g_sx)[j] = v;
    }
}

// User gather: 2 users per warp (16 lanes each, float4/lane). Partners are
// spots; rows pre-scaled. All-int indexing, no type branching.
__global__ void __launch_bounds__(256) user_gather_kernel(float* __restrict__ out) {
    int warp = (blockIdx.x * blockDim.x + threadIdx.x) >> 5;
    int lane = threadIdx.x & 31;
    int half16 = lane & 16;
    int col = lane & 15;

    int n = warp * 2 + (half16 >> 4);
    if (n >= N_USERS) return;

    const int* __restrict__ adj = g_adj_u + n * CAP_U;
    const ulonglong2* __restrict__ px = (const ulonglong2*)g_sx;
    int end = min(g_cnt[n], CAP_U);
    int max_end = max(end, __shfl_xor_sync(0xffffffffu, end, 16));

    unsigned long long acc0 = 0, acc1 = 0;

    for (int base = 0; base < max_end; base += 16) {
        int p = 0;
        if (base < end) p = __ldg(&adj[base + col]);
        #pragma unroll
        for (int k = 0; k < 16; ++k) {
            int pk = __shfl_sync(0xffffffffu, p, half16 + k);
            if (base + k < end) {
                ulonglong2 v = __ldg(&px[pk * D4 + col]);
                add_f32x2(acc0, v.x);
                add_f32x2(acc1, v.y);
            }
        }
    }

    float sc = g_isq[n];
    unsigned long long scp;
    asm("mov.b64 %0, {%1, %1};" : "=l"(scp) : "f"(sc));
    ulonglong2 r;
    r.x = mul_f32x2(acc0, scp);
    r.y = mul_f32x2(acc1, scp);
    ((ulonglong2*)out)[n * D4 + col] = r;   // user rows occupy out[0 .. N_USERS*D)
}

// Spot gather: ONE spot per warp; the two 16-lane halves take even/odd
// 16-chunks of the SAME node => warp-uniform end, no divergence waste.
__global__ void __launch_bounds__(256) spot_gather_kernel(float* __restrict__ out) {
    int n = (blockIdx.x * blockDim.x + threadIdx.x) >> 5;
    if (n >= N_SPOTS) return;
    int lane = threadIdx.x & 31;
    int half = lane >> 4;     // 0 or 1
    int half16 = lane & 16;
    int col = lane & 15;

    const int* __restrict__ adj = g_adj_s + n * CAP_S;
    const ulonglong2* __restrict__ px = (const ulonglong2*)g_ux;
    int end = min(g_cnt[N_USERS + n], CAP_S);

    int nchunks = (end + 15) >> 4;          // total 16-chunks
    int trips = (nchunks + 1) >> 1;         // per half (uniform)

    unsigned long long acc0 = 0, acc1 = 0;

    for (int it = 0; it < trips; ++it) {
        int base = (it * 2 + half) * 16;
        int p = 0;
        if (base + col < end) p = __ldg(&adj[base + col]);
        #pragma unroll
        for (int k = 0; k < 16; ++k) {
            int pk = __shfl_sync(0xffffffffu, p, half16 + k);
            if (base + k < end) {
                ulonglong2 v = __ldg(&px[pk * D4 + col]);
                add_f32x2(acc0, v.x);
                add_f32x2(acc1, v.y);
            }
        }
    }

    // Combine halves (same columns, disjoint edges).
    unsigned long long o0 = __shfl_xor_sync(0xffffffffu, acc0, 16);
    unsigned long long o1 = __shfl_xor_sync(0xffffffffu, acc1, 16);
    add_f32x2(acc0, o0);
    add_f32x2(acc1, o1);

    if (half == 0) {
        float sc = g_isq[N_USERS + n];
        unsigned long long scp;
        asm("mov.b64 %0, {%1, %1};" : "=l"(scp) : "f"(sc));
        ulonglong2 r;
        r.x = mul_f32x2(acc0, scp);
        r.y = mul_f32x2(acc1, scp);
        ((ulonglong2*)out)[(N_USERS + n) * D4 + col] = r;  // spot rows after users
    }
}

extern "C" void kernel_launch(void* const* d_in, const int* in_sizes, int n_in,
                              void* d_out, int out_size) {
    const float* user_x   = (const float*)d_in[0];
    const float* spot_x   = (const float*)d_in[1];
    const int*   user_idx = (const int*)d_in[2];
    const int*   spot_idx = (const int*)d_in[3];
    float* out = (float*)d_out;

    zero_kernel<<<(N_NODES + 255) / 256, 256>>>();

    int e4 = N_EDGES / 4;  // 800000
    fill_kernel<<<(e4 + 255) / 256, 256>>>((const int4*)user_idx, (const int4*)spot_idx);

    int ps_threads = N_NODES * D4;
    prescale_kernel<<<(ps_threads + 255) / 256, 256>>>(user_x, spot_x);

    int ug_blocks = ((N_USERS / 2) * 32 + 255) / 256;   // 2 users per warp
    user_gather_kernel<<<ug_blocks, 256>>>(out);

    int sg_blocks = (N_SPOTS * 32 + 255) / 256;         // 1 spot per warp
    spot_gather_kernel<<<sg_blocks, 256>>>(out);
}